// round 10
// baseline (speedup 1.0000x reference)
#include <cuda_runtime.h>
#include <math.h>
#include <stdint.h>

#define BATCH 2048
#define HDIM  1024
#define G3    3072
#define NMSG  4096

// ---------------- scratch (static device globals; no allocation) ----------------
__device__ float g_Hin[7LL * BATCH * HDIM];
__device__ float g_HinR[(long)BATCH * HDIM];      // tf32-rounded A for GRU1
__device__ float g_Hv[(long)BATCH * HDIM];
__device__ float g_HvR[(long)BATCH * HDIM];       // tf32-rounded A for GRU2/msg/out
__device__ float g_gh[(long)BATCH * G3];
__device__ float g_msg[(long)BATCH * NMSG];
__device__ float g_giAll[13LL * BATCH * G3];
__device__ float g_Xpad[13LL * BATCH * 32];       // rounded
__device__ float g_Wx32[3LL * G3 * 32];           // rounded
__device__ float g_Whh3R[3LL * G3 * HDIM];        // rounded hh weights [c|l|r]
__device__ float g_WmsgR[(long)NMSG * HDIM];      // rounded packed msg weights
__device__ float g_WoutR[512L * HDIM];            // rounded [Wmu;Wstd]
__device__ float g_bout[512];                     // packed [bmu;bstd]

__device__ __forceinline__ float sigmoidf(float x) { return 1.f / (1.f + expf(-x)); }
__device__ __forceinline__ float softplusf(float x) {
    return (x > 20.f) ? x : log1pf(expf(x));
}
__device__ __forceinline__ float rtf(float x) {
    unsigned u;
    asm("cvt.rna.tf32.f32 %0, %1;" : "=r"(u) : "f"(x));
    return __uint_as_float(u);
}

// ---------------- packing (all write tf32-rounded values) ----------------
__global__ void pack_xpad(const float* __restrict__ X, const int* __restrict__ adj,
                          float* __restrict__ Xp) {
    int idx = blockIdx.x * blockDim.x + threadIdx.x;
    if (idx >= 13 * BATCH * 32) return;
    int slot = idx / (BATCH * 32);
    int rem  = idx - slot * (BATCH * 32);
    int b = rem >> 5, k = rem & 31;
    float v = 0.f;
    if (slot < 6) {
        int node = slot + 1;
        if (k < 27) v = X[(long)b * 189 + node * 27 + k];
    } else if (slot < 12) {
        int node = slot - 5;
        if (k < 27 && adj[(long)b * 49 + node * 8] > 0)
            v = X[(long)b * 189 + node * 27 + k];
    } else {
        if (k < 23) v = X[(long)b * 189 + k];
    }
    Xp[idx] = rtf(v);
}

__global__ void pack_wx32(const float* __restrict__ W, float* __restrict__ P, int K) {
    int idx = blockIdx.x * blockDim.x + threadIdx.x;
    if (idx >= G3 * 32) return;
    int j = idx >> 5, k = idx & 31;
    P[idx] = (k < K) ? rtf(W[j * K + k]) : 0.f;
}

__global__ void pack_msgw(const float* __restrict__ Wg, const float* __restrict__ Wm,
                          float* __restrict__ P) {
    int idx = blockIdx.x * blockDim.x + threadIdx.x;
    int j = idx >> 10, k = idx & 1023;
    float v;
    if (j < 1024)       v = Wg[j * 2048 + k];
    else if (j < 2048)  v = Wg[(j - 1024) * 2048 + 1024 + k];
    else if (j < 3072)  v = Wm[(j - 2048) * 2048 + k];
    else                v = Wm[(j - 3072) * 2048 + 1024 + k];
    P[idx] = rtf(v);
}

// three equal-size segments rounded into one contiguous buffer
__global__ void round_copy3(const float* __restrict__ a, const float* __restrict__ b,
                            const float* __restrict__ c, float* __restrict__ out,
                            int n) {
    int idx = blockIdx.x * blockDim.x + threadIdx.x;
    if (idx >= 3 * n) return;
    int seg = idx / n, r = idx - seg * n;
    const float* src = (seg == 0) ? a : (seg == 1) ? b : c;
    out[idx] = rtf(src[r]);
}

// two equal-size segments
__global__ void round_copy2(const float* __restrict__ a, const float* __restrict__ b,
                            float* __restrict__ out, int n) {
    int idx = blockIdx.x * blockDim.x + threadIdx.x;
    if (idx >= 2 * n) return;
    out[idx] = rtf(idx < n ? a[idx] : b[idx - n]);
}

// ---------------- GRU elementwise combine (+ rounded copy) ----------------
// WRITE_HO=0 when the unrounded output is never consumed downstream.
template<int WRITE_HO>
__global__ __launch_bounds__(256) void gru_combine_r(
    const float* __restrict__ gi, const float* __restrict__ gh,
    const float* __restrict__ hp, float* __restrict__ ho,
    float* __restrict__ hoR)
{
    int idx = blockIdx.x * 256 + threadIdx.x;
    int b = idx >> 10, h = idx & 1023;
    long base = (long)b * G3 + h;
    float ir = gi[base], iz = gi[base + 1024], in_ = gi[base + 2048];
    float hr = gh[base], hz = gh[base + 1024], hn = gh[base + 2048];
    float r = sigmoidf(ir + hr);
    float z = sigmoidf(iz + hz);
    float n = tanhf(in_ + r * hn);
    float o = (1.f - z) * n + z * hp[idx];
    if (WRITE_HO) ho[idx] = o;
    hoR[idx] = rtf(o);
}

// v=6 GRU1: gh = bias (H_in = 0), hp = 0
__global__ __launch_bounds__(256) void gru_combine_bias(
    const float* __restrict__ gi, const float* __restrict__ bhh,
    float* __restrict__ ho, float* __restrict__ hoR)
{
    int idx = blockIdx.x * 256 + threadIdx.x;
    int b = idx >> 10, h = idx & 1023;
    long base = (long)b * G3 + h;
    float ir = gi[base], iz = gi[base + 1024], in_ = gi[base + 2048];
    float hr = bhh[h], hz = bhh[1024 + h], hn = bhh[2048 + h];
    float r = sigmoidf(ir + hr);
    float z = sigmoidf(iz + hz);
    float n = tanhf(in_ + r * hn);
    float o = (1.f - z) * n;
    ho[idx]  = o;      // needed as hp of v=6 GRU2
    hoR[idx] = rtf(o);
}

// ---------------- message push: precompute 3 combos, select per receiver ----------
__global__ __launch_bounds__(256) void msg_scatter_all(
    const float* __restrict__ Mg, const int* __restrict__ adj,
    const float* __restrict__ bg, float* __restrict__ HinBase,
    float* __restrict__ HinR, int S)
{
    int idx = blockIdx.x * 256 + threadIdx.x;
    int b = idx >> 10, h = idx & 1023;
    const float* M = Mg + (long)b * NMSG;
    float Av = M[h], Bv = M[1024 + h], Cv = M[2048 + h], Dv = M[3072 + h];
    float bgh = bg[h];
    float c10 = sigmoidf(Av + bgh) * Cv;
    float c01 = sigmoidf(Bv + bgh) * Dv;
    float c11 = sigmoidf(Av + Bv + bgh) * (Cv + Dv);
    const int* arow = adj + (long)b * 49;
    for (int u = 0; u < S; u++) {
        bool fp = arow[S * 7 + u] > 0;
        bool fs = arow[u * 7 + S] > 0;
        float add = fp ? (fs ? c11 : c10) : (fs ? c01 : 0.f);
        long o = (long)u * BATCH * HDIM + idx;
        float val = HinBase[o] + add;
        HinBase[o] = val;
        if (u == S - 1) HinR[idx] = rtf(val);
    }
}

// ---------------- TF32 mma.sync GEMM (BN=128, pre-rounded operands) ----------------
#define BM 128
#define BN 128
#define BK 16
#define KS 20

__global__ __launch_bounds__(256, 2) void tgemm_nt(
    const float* __restrict__ A, const float* __restrict__ B,
    const float* __restrict__ bias, float* __restrict__ C,
    int N, int K, int act)
{
    __shared__ unsigned As[2][BM][KS];
    __shared__ unsigned Bs[2][BN][KS];

    const int tid  = threadIdx.x;
    const int lane = tid & 31;
    const int warp = tid >> 5;
    const int wm   = warp >> 1;
    const int wn   = warp & 1;
    const long bm  = (long)blockIdx.y * BM;
    const long bn  = (long)blockIdx.x * BN;

    const int lrow = tid >> 2;            // 0..63
    const int lcol = (tid & 3) << 2;      // 0,4,8,12
    const float* Aptr = A + (bm + lrow) * K + lcol;
    const float* Bptr = B + (bn + lrow) * K + lcol;

    float acc[2][8][4];
#pragma unroll
    for (int i = 0; i < 2; i++)
#pragma unroll
        for (int j = 0; j < 8; j++)
#pragma unroll
            for (int q = 0; q < 4; q++) acc[i][j][q] = 0.f;

    {
#pragma unroll
        for (int r = 0; r < 2; r++) {
            *(uint4*)&As[0][lrow + r * 64][lcol] =
                *(const uint4*)(Aptr + (long)(r * 64) * K);
            *(uint4*)&Bs[0][lrow + r * 64][lcol] =
                *(const uint4*)(Bptr + (long)(r * 64) * K);
        }
    }
    __syncthreads();

    const int nt = K / BK;
    const int gr = lane >> 2;
    const int gk = lane & 3;
    uint4 pa[2], pb[2];

    for (int t = 0; t < nt; t++) {
        const int cur = t & 1, nxt = cur ^ 1;
        const bool more = (t + 1 < nt);
        if (more) {
            int koff = (t + 1) * BK;
#pragma unroll
            for (int r = 0; r < 2; r++) {
                pa[r] = *(const uint4*)(Aptr + (long)(r * 64) * K + koff);
                pb[r] = *(const uint4*)(Bptr + (long)(r * 64) * K + koff);
            }
        }
#pragma unroll
        for (int k8 = 0; k8 < 2; k8++) {
            const int kb = k8 * 8;
            unsigned a[2][4], b[8][2];
#pragma unroll
            for (int mt = 0; mt < 2; mt++) {
                int m = wm * 32 + mt * 16 + gr;
                a[mt][0] = As[cur][m][kb + gk];
                a[mt][1] = As[cur][m + 8][kb + gk];
                a[mt][2] = As[cur][m][kb + gk + 4];
                a[mt][3] = As[cur][m + 8][kb + gk + 4];
            }
#pragma unroll
            for (int ntile = 0; ntile < 8; ntile++) {
                int n = wn * 64 + ntile * 8 + gr;
                b[ntile][0] = Bs[cur][n][kb + gk];
                b[ntile][1] = Bs[cur][n][kb + gk + 4];
            }
#pragma unroll
            for (int mt = 0; mt < 2; mt++)
#pragma unroll
                for (int ntile = 0; ntile < 8; ntile++) {
                    asm volatile(
                        "mma.sync.aligned.m16n8k8.row.col.f32.tf32.tf32.f32 "
                        "{%0,%1,%2,%3}, {%4,%5,%6,%7}, {%8,%9}, {%0,%1,%2,%3};\n"
                        : "+f"(acc[mt][ntile][0]), "+f"(acc[mt][ntile][1]),
                          "+f"(acc[mt][ntile][2]), "+f"(acc[mt][ntile][3])
                        : "r"(a[mt][0]), "r"(a[mt][1]), "r"(a[mt][2]), "r"(a[mt][3]),
                          "r"(b[ntile][0]), "r"(b[ntile][1]));
                }
        }
        if (more) {
#pragma unroll
            for (int r = 0; r < 2; r++) {
                *(uint4*)&As[nxt][lrow + r * 64][lcol] = pa[r];
                *(uint4*)&Bs[nxt][lrow + r * 64][lcol] = pb[r];
            }
        }
        __syncthreads();
    }

    const int gc2 = (lane & 3) * 2;
#pragma unroll
    for (int mt = 0; mt < 2; mt++) {
        long row0 = bm + wm * 32 + mt * 16 + gr;
#pragma unroll
        for (int ntile = 0; ntile < 8; ntile++) {
            int col = bn + wn * 64 + ntile * 8 + gc2;
            float b0 = bias ? bias[col] : 0.f;
            float b1 = bias ? bias[col + 1] : 0.f;
            float2 v0, v1;
            v0.x = acc[mt][ntile][0] + b0; v0.y = acc[mt][ntile][1] + b1;
            v1.x = acc[mt][ntile][2] + b0; v1.y = acc[mt][ntile][3] + b1;
            if (act == 2) {
                float* dst;
                if (col < 256) {
                    dst = C + row0 * 256 + col;
                } else {
                    dst = C + 2048L * 256 + row0 * 256 + (col - 256);
                    v0.x = softplusf(v0.x); v0.y = softplusf(v0.y);
                    v1.x = softplusf(v1.x); v1.y = softplusf(v1.y);
                }
                *(float2*)dst             = v0;
                *(float2*)(dst + 8 * 256) = v1;
            } else {
                *(float2*)(C + row0 * N + col)       = v0;
                *(float2*)(C + (row0 + 8) * N + col) = v1;
            }
        }
    }
}

// ---------------- orchestration ----------------
extern "C" void kernel_launch(void* const* d_in, const int* in_sizes, int n_in,
                              void* d_out, int out_size)
{
    const float* X      = (const float*)d_in[0];
    const int*   adj    = (const int*)  d_in[1];
    const float* W_ih_c = (const float*)d_in[2];
    const float* W_hh_c = (const float*)d_in[3];
    const float* b_ih_c = (const float*)d_in[4];
    const float* b_hh_c = (const float*)d_in[5];
    const float* W_ih_l = (const float*)d_in[6];
    const float* W_hh_l = (const float*)d_in[7];
    const float* b_ih_l = (const float*)d_in[8];
    const float* b_hh_l = (const float*)d_in[9];
    const float* W_ih_r = (const float*)d_in[10];
    const float* W_hh_r = (const float*)d_in[11];
    const float* b_ih_r = (const float*)d_in[12];
    const float* b_hh_r = (const float*)d_in[13];
    const float* Wg     = (const float*)d_in[14];
    const float* bg     = (const float*)d_in[15];
    const float* Wm     = (const float*)d_in[16];
    const float* Wmu    = (const float*)d_in[17];
    const float* bmu    = (const float*)d_in[18];
    const float* Wstd   = (const float*)d_in[19];
    const float* bstd   = (const float*)d_in[20];

    float *Hin, *HinR, *Hv, *HvR, *gh, *msg, *giAll, *Xpad, *Wx32;
    float *Whh3R, *WmsgR, *WoutR, *bout;
    cudaGetSymbolAddress((void**)&Hin,   g_Hin);
    cudaGetSymbolAddress((void**)&HinR,  g_HinR);
    cudaGetSymbolAddress((void**)&Hv,    g_Hv);
    cudaGetSymbolAddress((void**)&HvR,   g_HvR);
    cudaGetSymbolAddress((void**)&gh,    g_gh);
    cudaGetSymbolAddress((void**)&msg,   g_msg);
    cudaGetSymbolAddress((void**)&giAll, g_giAll);
    cudaGetSymbolAddress((void**)&Xpad,  g_Xpad);
    cudaGetSymbolAddress((void**)&Wx32,  g_Wx32);
    cudaGetSymbolAddress((void**)&Whh3R, g_Whh3R);
    cudaGetSymbolAddress((void**)&WmsgR, g_WmsgR);
    cudaGetSymbolAddress((void**)&WoutR, g_WoutR);
    cudaGetSymbolAddress((void**)&bout,  g_bout);

    float* WhhcR = Whh3R;
    float* WhhlR = Whh3R + (long)G3 * HDIM;
    float* WhhrR = Whh3R + 2L * G3 * HDIM;

    cudaMemsetAsync(Hin, 0, sizeof(float) * 7LL * BATCH * HDIM, 0);

    pack_xpad<<<(13 * BATCH * 32) / 256, 256>>>(X, adj, Xpad);
    pack_wx32<<<(G3 * 32) / 256, 256>>>(W_ih_c, Wx32,               27);
    pack_wx32<<<(G3 * 32) / 256, 256>>>(W_ih_l, Wx32 + (long)G3*32, 27);
    pack_wx32<<<(G3 * 32) / 256, 256>>>(W_ih_r, Wx32 + 2L*G3*32,    23);
    pack_msgw<<<(NMSG * HDIM) / 256, 256>>>(Wg, Wm, WmsgR);

    round_copy3<<<(3 * G3 * HDIM) / 256, 256>>>(W_hh_c, W_hh_l, W_hh_r,
                                                Whh3R, G3 * HDIM);
    round_copy2<<<(2 * 256 * HDIM) / 256, 256>>>(Wmu, Wstd, WoutR, 256 * HDIM);
    cudaMemcpyAsync(bout,       bmu,  256 * sizeof(float), cudaMemcpyDeviceToDevice, 0);
    cudaMemcpyAsync(bout + 256, bstd, 256 * sizeof(float), cudaMemcpyDeviceToDevice, 0);

    // gi projections (K=32)
    const long SEG = 6LL * BATCH;
    dim3 gGI6(G3 / BN, (6 * BATCH) / BM);
    dim3 gGI1(G3 / BN, BATCH / BM);
    tgemm_nt<<<gGI6, 256>>>(Xpad,                Wx32,               b_ih_c,
                            giAll,               G3, 32, 0);
    tgemm_nt<<<gGI6, 256>>>(Xpad + SEG * 32,     Wx32 + (long)G3*32, b_ih_l,
                            giAll + SEG * G3,    G3, 32, 0);
    tgemm_nt<<<gGI1, 256>>>(Xpad + 2 * SEG * 32, Wx32 + 2L*G3*32,    b_ih_r,
                            giAll + 2 * SEG * G3, G3, 32, 0);

    dim3 gGH(G3 / BN, BATCH / BM);             // (24, 16)
    dim3 gMS(NMSG / BN, BATCH / BM);           // (32, 16)
    dim3 gOUT(512 / BN, BATCH / BM);           // (4, 16)
    const int EW = (BATCH * HDIM) / 256;       // 8192

    for (int v = 6; v >= 0; v--) {
        const float* WhhR = (v == 0) ? WhhrR : WhhcR;
        const float* bhh  = (v == 0) ? b_hh_r : b_hh_c;
        const float* gi1  = (v == 0) ? (giAll + 2 * SEG * G3)
                                     : (giAll + (long)(v - 1) * BATCH * G3);

        // GRU 1
        if (v == 6) {
            gru_combine_bias<<<EW, 256>>>(gi1, bhh, Hv, HvR);
        } else {
            float* Hin_v = Hin + (long)v * BATCH * HDIM;
            tgemm_nt<<<gGH, 256>>>(HinR, WhhR, bhh, gh, G3, HDIM, 0);
            if (v == 0) {
                // unrounded output never consumed (only HvR feeds the out GEMM)
                gru_combine_r<0><<<EW, 256>>>(gi1, gh, Hin_v, Hv, HvR);
            } else {
                gru_combine_r<1><<<EW, 256>>>(gi1, gh, Hin_v, Hv, HvR);
            }
        }

        if (v > 0) {
            // GRU 2 (self-loop): unrounded output never consumed (HvR feeds msg GEMM)
            const float* gi2 = giAll + (SEG + (long)(v - 1) * BATCH) * G3;
            tgemm_nt<<<gGH, 256>>>(HvR, WhhlR, b_hh_l, gh, G3, HDIM, 0);
            gru_combine_r<0><<<EW, 256>>>(gi2, gh, Hv, Hv, HvR);

            // sender projections, then push to receivers (fused tf32 round for u=v-1)
            tgemm_nt<<<gMS, 256>>>(HvR, WmsgR, nullptr, msg, NMSG, HDIM, 0);
            msg_scatter_all<<<EW, 256>>>(msg, adj, bg, Hin, HinR, v);
        }
    }

    // fused mu/std output GEMM (act=2 split epilogue)
    tgemm_nt<<<gOUT, 256>>>(HvR, WoutR, bout, (float*)d_out, 512, HDIM, 2);
}

// round 11
// speedup vs baseline: 1.6751x; 1.6751x over previous
#include <cuda_runtime.h>
#include <cuda_fp16.h>
#include <math.h>
#include <stdint.h>

#define BATCH 2048
#define HDIM  1024
#define G3    3072
#define NMSG  4096

// ---------------- scratch (static device globals; no allocation) ----------------
__device__ float g_Hin[7LL * BATCH * HDIM];
__device__ float g_Hv[(long)BATCH * HDIM];
__device__ float g_gh[(long)BATCH * G3];
__device__ float g_msg[(long)BATCH * NMSG];
__device__ float g_giAll[13LL * BATCH * G3];
__device__ __align__(16) __half g_HinR[(long)BATCH * HDIM];   // fp16 A for GRU1
__device__ __align__(16) __half g_HvR[(long)BATCH * HDIM];    // fp16 A for GRU2/msg/out
__device__ __align__(16) __half g_Xpad[13LL * BATCH * 32];
__device__ __align__(16) __half g_Wx32[3LL * G3 * 32];
__device__ __align__(16) __half g_Whh3R[3LL * G3 * HDIM];     // [c|l|r]
__device__ __align__(16) __half g_WmsgR[(long)NMSG * HDIM];
__device__ __align__(16) __half g_WoutR[512L * HDIM];         // [Wmu;Wstd]
__device__ float g_bout[512];                                  // [bmu;bstd]

__device__ __forceinline__ float sigmoidf(float x) { return 1.f / (1.f + expf(-x)); }
__device__ __forceinline__ float softplusf(float x) {
    return (x > 20.f) ? x : log1pf(expf(x));
}

// ---------------- packing (emit fp16 operands) ----------------
__global__ void pack_xpad(const float* __restrict__ X, const int* __restrict__ adj,
                          __half* __restrict__ Xp) {
    int idx = blockIdx.x * blockDim.x + threadIdx.x;
    if (idx >= 13 * BATCH * 32) return;
    int slot = idx / (BATCH * 32);
    int rem  = idx - slot * (BATCH * 32);
    int b = rem >> 5, k = rem & 31;
    float v = 0.f;
    if (slot < 6) {
        int node = slot + 1;
        if (k < 27) v = X[(long)b * 189 + node * 27 + k];
    } else if (slot < 12) {
        int node = slot - 5;
        if (k < 27 && adj[(long)b * 49 + node * 8] > 0)
            v = X[(long)b * 189 + node * 27 + k];
    } else {
        if (k < 23) v = X[(long)b * 189 + k];
    }
    Xp[idx] = __float2half_rn(v);
}

__global__ void pack_wx32(const float* __restrict__ W, __half* __restrict__ P, int K) {
    int idx = blockIdx.x * blockDim.x + threadIdx.x;
    if (idx >= G3 * 32) return;
    int j = idx >> 5, k = idx & 31;
    P[idx] = __float2half_rn((k < K) ? W[j * K + k] : 0.f);
}

__global__ void pack_msgw(const float* __restrict__ Wg, const float* __restrict__ Wm,
                          __half* __restrict__ P) {
    int idx = blockIdx.x * blockDim.x + threadIdx.x;
    int j = idx >> 10, k = idx & 1023;
    float v;
    if (j < 1024)       v = Wg[j * 2048 + k];
    else if (j < 2048)  v = Wg[(j - 1024) * 2048 + 1024 + k];
    else if (j < 3072)  v = Wm[(j - 2048) * 2048 + k];
    else                v = Wm[(j - 3072) * 2048 + 1024 + k];
    P[idx] = __float2half_rn(v);
}

__global__ void half_copy3(const float* __restrict__ a, const float* __restrict__ b,
                           const float* __restrict__ c, __half* __restrict__ out,
                           int n) {
    int idx = blockIdx.x * blockDim.x + threadIdx.x;
    if (idx >= 3 * n) return;
    int seg = idx / n, r = idx - seg * n;
    const float* src = (seg == 0) ? a : (seg == 1) ? b : c;
    out[idx] = __float2half_rn(src[r]);
}

__global__ void half_copy2(const float* __restrict__ a, const float* __restrict__ b,
                           __half* __restrict__ out, int n) {
    int idx = blockIdx.x * blockDim.x + threadIdx.x;
    if (idx >= 2 * n) return;
    out[idx] = __float2half_rn(idx < n ? a[idx] : b[idx - n]);
}

// ---------------- GRU elementwise combine (+ fp16 copy) ----------------
template<int WRITE_HO>
__global__ __launch_bounds__(256) void gru_combine_r(
    const float* __restrict__ gi, const float* __restrict__ gh,
    const float* __restrict__ hp, float* __restrict__ ho,
    __half* __restrict__ hoR)
{
    int idx = blockIdx.x * 256 + threadIdx.x;
    int b = idx >> 10, h = idx & 1023;
    long base = (long)b * G3 + h;
    float ir = gi[base], iz = gi[base + 1024], in_ = gi[base + 2048];
    float hr = gh[base], hz = gh[base + 1024], hn = gh[base + 2048];
    float r = sigmoidf(ir + hr);
    float z = sigmoidf(iz + hz);
    float n = tanhf(in_ + r * hn);
    float o = (1.f - z) * n + z * hp[idx];
    if (WRITE_HO) ho[idx] = o;
    hoR[idx] = __float2half_rn(o);
}

// v=6 GRU1: gh = bias (H_in = 0), hp = 0
__global__ __launch_bounds__(256) void gru_combine_bias(
    const float* __restrict__ gi, const float* __restrict__ bhh,
    float* __restrict__ ho, __half* __restrict__ hoR)
{
    int idx = blockIdx.x * 256 + threadIdx.x;
    int b = idx >> 10, h = idx & 1023;
    long base = (long)b * G3 + h;
    float ir = gi[base], iz = gi[base + 1024], in_ = gi[base + 2048];
    float hr = bhh[h], hz = bhh[1024 + h], hn = bhh[2048 + h];
    float r = sigmoidf(ir + hr);
    float z = sigmoidf(iz + hz);
    float n = tanhf(in_ + r * hn);
    float o = (1.f - z) * n;
    ho[idx]  = o;
    hoR[idx] = __float2half_rn(o);
}

// ---------------- message push: precompute 3 combos, select per receiver ----------
__global__ __launch_bounds__(256) void msg_scatter_all(
    const float* __restrict__ Mg, const int* __restrict__ adj,
    const float* __restrict__ bg, float* __restrict__ HinBase,
    __half* __restrict__ HinR, int S)
{
    int idx = blockIdx.x * 256 + threadIdx.x;
    int b = idx >> 10, h = idx & 1023;
    const float* M = Mg + (long)b * NMSG;
    float Av = M[h], Bv = M[1024 + h], Cv = M[2048 + h], Dv = M[3072 + h];
    float bgh = bg[h];
    float c10 = sigmoidf(Av + bgh) * Cv;
    float c01 = sigmoidf(Bv + bgh) * Dv;
    float c11 = sigmoidf(Av + Bv + bgh) * (Cv + Dv);
    const int* arow = adj + (long)b * 49;
    for (int u = 0; u < S; u++) {
        bool fp = arow[S * 7 + u] > 0;
        bool fs = arow[u * 7 + S] > 0;
        float add = fp ? (fs ? c11 : c10) : (fs ? c01 : 0.f);
        long o = (long)u * BATCH * HDIM + idx;
        float val = HinBase[o] + add;
        HinBase[o] = val;
        if (u == S - 1) HinR[idx] = __float2half_rn(val);
    }
}

// ---------------- fp16 mma.sync GEMM: C[M,N] = A[M,K] * B[N,K]^T ----------------
// A,B fp16, accum/output fp32. BM=128, BN=128, BK=32 halves (=16 u32 + 4 pad).
// act: 0=none, 2=split mu/std epilogue. K in halves (multiple of 32).
#define BM 128
#define BN 128
#define KS 20   // row stride in u32 (16 data + 4 pad, conflict-free)

__global__ __launch_bounds__(256, 2) void hgemm_nt(
    const __half* __restrict__ A, const __half* __restrict__ B,
    const float* __restrict__ bias, float* __restrict__ C,
    int N, int K, int act)
{
    __shared__ unsigned As[2][BM][KS];
    __shared__ unsigned Bs[2][BN][KS];

    const int tid  = threadIdx.x;
    const int lane = tid & 31;
    const int warp = tid >> 5;
    const int wm   = warp >> 1;
    const int wn   = warp & 1;
    const long bm  = (long)blockIdx.y * BM;
    const long bn  = (long)blockIdx.x * BN;

    const int lrow = tid >> 2;              // 0..63
    const int lcolh = (tid & 3) << 3;       // half offset 0,8,16,24 (16B chunks)
    const int lcolu = (tid & 3) << 2;       // u32 offset 0,4,8,12
    const __half* Aptr = A + (bm + lrow) * K + lcolh;
    const __half* Bptr = B + (bn + lrow) * K + lcolh;

    float acc[2][8][4];
#pragma unroll
    for (int i = 0; i < 2; i++)
#pragma unroll
        for (int j = 0; j < 8; j++)
#pragma unroll
            for (int q = 0; q < 4; q++) acc[i][j][q] = 0.f;

    // preload tile 0
    {
#pragma unroll
        for (int r = 0; r < 2; r++) {
            *(uint4*)&As[0][lrow + r * 64][lcolu] =
                *(const uint4*)(Aptr + (long)(r * 64) * K);
            *(uint4*)&Bs[0][lrow + r * 64][lcolu] =
                *(const uint4*)(Bptr + (long)(r * 64) * K);
        }
    }
    __syncthreads();

    const int nt = K / 32;
    const int gr = lane >> 2;
    const int gk = lane & 3;
    uint4 pa[2], pb[2];

    for (int t = 0; t < nt; t++) {
        const int cur = t & 1, nxt = cur ^ 1;
        const bool more = (t + 1 < nt);
        if (more) {
            int koff = (t + 1) * 32;        // halves
#pragma unroll
            for (int r = 0; r < 2; r++) {
                pa[r] = *(const uint4*)(Aptr + (long)(r * 64) * K + koff);
                pb[r] = *(const uint4*)(Bptr + (long)(r * 64) * K + koff);
            }
        }
#pragma unroll
        for (int k16 = 0; k16 < 2; k16++) {
            const int kb = k16 * 8;         // u32 offset of this k16 step
            unsigned a[2][4], b[8][2];
#pragma unroll
            for (int mt = 0; mt < 2; mt++) {
                int m = wm * 32 + mt * 16 + gr;
                a[mt][0] = As[cur][m][kb + gk];
                a[mt][1] = As[cur][m + 8][kb + gk];
                a[mt][2] = As[cur][m][kb + gk + 4];
                a[mt][3] = As[cur][m + 8][kb + gk + 4];
            }
#pragma unroll
            for (int ntile = 0; ntile < 8; ntile++) {
                int n = wn * 64 + ntile * 8 + gr;
                b[ntile][0] = Bs[cur][n][kb + gk];
                b[ntile][1] = Bs[cur][n][kb + gk + 4];
            }
#pragma unroll
            for (int mt = 0; mt < 2; mt++)
#pragma unroll
                for (int ntile = 0; ntile < 8; ntile++) {
                    asm volatile(
                        "mma.sync.aligned.m16n8k16.row.col.f32.f16.f16.f32 "
                        "{%0,%1,%2,%3}, {%4,%5,%6,%7}, {%8,%9}, {%0,%1,%2,%3};\n"
                        : "+f"(acc[mt][ntile][0]), "+f"(acc[mt][ntile][1]),
                          "+f"(acc[mt][ntile][2]), "+f"(acc[mt][ntile][3])
                        : "r"(a[mt][0]), "r"(a[mt][1]), "r"(a[mt][2]), "r"(a[mt][3]),
                          "r"(b[ntile][0]), "r"(b[ntile][1]));
                }
        }
        if (more) {
#pragma unroll
            for (int r = 0; r < 2; r++) {
                *(uint4*)&As[nxt][lrow + r * 64][lcolu] = pa[r];
                *(uint4*)&Bs[nxt][lrow + r * 64][lcolu] = pb[r];
            }
        }
        __syncthreads();
    }

    // epilogue
    const int gc2 = (lane & 3) * 2;
#pragma unroll
    for (int mt = 0; mt < 2; mt++) {
        long row0 = bm + wm * 32 + mt * 16 + gr;
#pragma unroll
        for (int ntile = 0; ntile < 8; ntile++) {
            int col = bn + wn * 64 + ntile * 8 + gc2;
            float b0 = bias ? bias[col] : 0.f;
            float b1 = bias ? bias[col + 1] : 0.f;
            float2 v0, v1;
            v0.x = acc[mt][ntile][0] + b0; v0.y = acc[mt][ntile][1] + b1;
            v1.x = acc[mt][ntile][2] + b0; v1.y = acc[mt][ntile][3] + b1;
            if (act == 2) {
                float* dst;
                if (col < 256) {
                    dst = C + row0 * 256 + col;
                } else {
                    dst = C + 2048L * 256 + row0 * 256 + (col - 256);
                    v0.x = softplusf(v0.x); v0.y = softplusf(v0.y);
                    v1.x = softplusf(v1.x); v1.y = softplusf(v1.y);
                }
                *(float2*)dst             = v0;
                *(float2*)(dst + 8 * 256) = v1;
            } else {
                *(float2*)(C + row0 * N + col)       = v0;
                *(float2*)(C + (row0 + 8) * N + col) = v1;
            }
        }
    }
}

// ---------------- orchestration ----------------
extern "C" void kernel_launch(void* const* d_in, const int* in_sizes, int n_in,
                              void* d_out, int out_size)
{
    const float* X      = (const float*)d_in[0];
    const int*   adj    = (const int*)  d_in[1];
    const float* W_ih_c = (const float*)d_in[2];
    const float* W_hh_c = (const float*)d_in[3];
    const float* b_ih_c = (const float*)d_in[4];
    const float* b_hh_c = (const float*)d_in[5];
    const float* W_ih_l = (const float*)d_in[6];
    const float* W_hh_l = (const float*)d_in[7];
    const float* b_ih_l = (const float*)d_in[8];
    const float* b_hh_l = (const float*)d_in[9];
    const float* W_ih_r = (const float*)d_in[10];
    const float* W_hh_r = (const float*)d_in[11];
    const float* b_ih_r = (const float*)d_in[12];
    const float* b_hh_r = (const float*)d_in[13];
    const float* Wg     = (const float*)d_in[14];
    const float* bg     = (const float*)d_in[15];
    const float* Wm     = (const float*)d_in[16];
    const float* Wmu    = (const float*)d_in[17];
    const float* bmu    = (const float*)d_in[18];
    const float* Wstd   = (const float*)d_in[19];
    const float* bstd   = (const float*)d_in[20];

    float *Hin, *Hv, *gh, *msg, *giAll, *bout;
    __half *HinR, *HvR, *Xpad, *Wx32, *Whh3R, *WmsgR, *WoutR;
    cudaGetSymbolAddress((void**)&Hin,   g_Hin);
    cudaGetSymbolAddress((void**)&Hv,    g_Hv);
    cudaGetSymbolAddress((void**)&gh,    g_gh);
    cudaGetSymbolAddress((void**)&msg,   g_msg);
    cudaGetSymbolAddress((void**)&giAll, g_giAll);
    cudaGetSymbolAddress((void**)&bout,  g_bout);
    cudaGetSymbolAddress((void**)&HinR,  g_HinR);
    cudaGetSymbolAddress((void**)&HvR,   g_HvR);
    cudaGetSymbolAddress((void**)&Xpad,  g_Xpad);
    cudaGetSymbolAddress((void**)&Wx32,  g_Wx32);
    cudaGetSymbolAddress((void**)&Whh3R, g_Whh3R);
    cudaGetSymbolAddress((void**)&WmsgR, g_WmsgR);
    cudaGetSymbolAddress((void**)&WoutR, g_WoutR);

    __half* WhhcR = Whh3R;
    __half* WhhlR = Whh3R + (long)G3 * HDIM;
    __half* WhhrR = Whh3R + 2L * G3 * HDIM;

    cudaMemsetAsync(Hin, 0, sizeof(float) * 7LL * BATCH * HDIM, 0);

    pack_xpad<<<(13 * BATCH * 32) / 256, 256>>>(X, adj, Xpad);
    pack_wx32<<<(G3 * 32) / 256, 256>>>(W_ih_c, Wx32,               27);
    pack_wx32<<<(G3 * 32) / 256, 256>>>(W_ih_l, Wx32 + (long)G3*32, 27);
    pack_wx32<<<(G3 * 32) / 256, 256>>>(W_ih_r, Wx32 + 2L*G3*32,    23);
    pack_msgw<<<(NMSG * HDIM) / 256, 256>>>(Wg, Wm, WmsgR);

    half_copy3<<<(3 * G3 * HDIM) / 256, 256>>>(W_hh_c, W_hh_l, W_hh_r,
                                               Whh3R, G3 * HDIM);
    half_copy2<<<(2 * 256 * HDIM) / 256, 256>>>(Wmu, Wstd, WoutR, 256 * HDIM);
    cudaMemcpyAsync(bout,       bmu,  256 * sizeof(float), cudaMemcpyDeviceToDevice, 0);
    cudaMemcpyAsync(bout + 256, bstd, 256 * sizeof(float), cudaMemcpyDeviceToDevice, 0);

    // gi projections (K=32 halves -> single K-tile)
    const long SEG = 6LL * BATCH;
    dim3 gGI6(G3 / BN, (6 * BATCH) / BM);
    dim3 gGI1(G3 / BN, BATCH / BM);
    hgemm_nt<<<gGI6, 256>>>(Xpad,                Wx32,               b_ih_c,
                            giAll,               G3, 32, 0);
    hgemm_nt<<<gGI6, 256>>>(Xpad + SEG * 32,     Wx32 + (long)G3*32, b_ih_l,
                            giAll + SEG * G3,    G3, 32, 0);
    hgemm_nt<<<gGI1, 256>>>(Xpad + 2 * SEG * 32, Wx32 + 2L*G3*32,    b_ih_r,
                            giAll + 2 * SEG * G3, G3, 32, 0);

    dim3 gGH(G3 / BN, BATCH / BM);             // (24, 16)
    dim3 gMS(NMSG / BN, BATCH / BM);           // (32, 16)
    dim3 gOUT(512 / BN, BATCH / BM);           // (4, 16)
    const int EW = (BATCH * HDIM) / 256;       // 8192

    for (int v = 6; v >= 0; v--) {
        const __half* WhhR = (v == 0) ? WhhrR : WhhcR;
        const float* bhh   = (v == 0) ? b_hh_r : b_hh_c;
        const float* gi1   = (v == 0) ? (giAll + 2 * SEG * G3)
                                      : (giAll + (long)(v - 1) * BATCH * G3);

        // GRU 1
        if (v == 6) {
            gru_combine_bias<<<EW, 256>>>(gi1, bhh, Hv, HvR);
        } else {
            float* Hin_v = Hin + (long)v * BATCH * HDIM;
            hgemm_nt<<<gGH, 256>>>(HinR, WhhR, bhh, gh, G3, HDIM, 0);
            if (v == 0) {
                gru_combine_r<0><<<EW, 256>>>(gi1, gh, Hin_v, Hv, HvR);
            } else {
                gru_combine_r<1><<<EW, 256>>>(gi1, gh, Hin_v, Hv, HvR);
            }
        }

        if (v > 0) {
            // GRU 2 (self-loop)
            const float* gi2 = giAll + (SEG + (long)(v - 1) * BATCH) * G3;
            hgemm_nt<<<gGH, 256>>>(HvR, WhhlR, b_hh_l, gh, G3, HDIM, 0);
            gru_combine_r<0><<<EW, 256>>>(gi2, gh, Hv, Hv, HvR);

            // sender projections, then push to receivers (fused fp16 round for u=v-1)
            hgemm_nt<<<gMS, 256>>>(HvR, WmsgR, nullptr, msg, NMSG, HDIM, 0);
            msg_scatter_all<<<EW, 256>>>(msg, adj, bg, Hin, HinR, v);
        }
    }

    // fused mu/std output GEMM (act=2 split epilogue)
    hgemm_nt<<<gOUT, 256>>>(HvR, WoutR, bout, (float*)d_out, 512, HDIM, 2);
}